// round 6
// baseline (speedup 1.0000x reference)
#include <cuda_runtime.h>
#include <cstdint>

// Causal unbiased-EMA instance norm, x: [B=8, C=256, T=16384] fp32 — EXACT
// via per-lane block decomposition + affine prefix scan.
//
//   s1 = a*s1 + (1-a)*x ; s2 = a*s2 + (1-a)*x^2 ; w = a*w + (1-a)
//   y  = (w*x - s1) * rsqrt(max(w*s2 - s1^2, 0) + eps*w^2)
//
// One block per (b,c) lane, 512 threads x 32 steps. Segment EMA state is
// affine in the incoming state with decay A = a^32 -> affine scan gives each
// thread its exact start state; the multiplier prefix gives w0 = 1 - a^{t0}.
//
// R6: TPB 256->512 (KP 64->32). Same ~72KB smem -> still 3 blocks/SM but
// 48 resident warps (75% occ) for latency hiding / phase overlap.
// Data movement stays fully vectorized: cp.async.cg 16B loads, LDS.128 /
// STS.128 passes, LDS.128+STG.128 store. 16B pad per 32-float row keeps
// float4 alignment and bank-conflict-freedom for all access patterns.

#define T_LEN  16384
#define TPB    512
#define KP     (T_LEN / TPB)     // 32 steps per thread
#define NWARP  (TPB / 32)        // 16

#define ALPHA_F 0.99f
#define OMA_F   0.01f
#define EPS_F   1e-5f
#define A32_F   0.72498036f      // 0.99^32

#define PAD(i)  ((i) + (((i) >> 5) << 2))      // +4 floats (16B) per 32-row
#define SMEM_F  (T_LEN + ((T_LEN >> 5) << 2))  // 18432 floats = 73728 B

__device__ __forceinline__ void cp_async16(float* smem_dst, const float* gmem_src) {
    uint32_t s = (uint32_t)__cvta_generic_to_shared(smem_dst);
    asm volatile("cp.async.cg.shared.global [%0], [%1], 16;" :: "r"(s), "l"(gmem_src));
}

__device__ __forceinline__ void warm_step(float xi, float& s1, float& s2) {
    float t = OMA_F * xi;
    s1 = fmaf(ALPHA_F, s1, t);
    s2 = fmaf(ALPHA_F, s2, t * xi);
}

__device__ __forceinline__ float ema_step(float xi, float& s1, float& s2, float& w) {
    float t = OMA_F * xi;
    s1 = fmaf(ALPHA_F, s1, t);
    s2 = fmaf(ALPHA_F, s2, t * xi);
    w  = fmaf(ALPHA_F, w, OMA_F);
    float num   = fmaf(w, xi, -s1);
    float dcore = fmaf(w, s2, -(s1 * s1));
    dcore = fmaxf(dcore, 0.0f);               // t=1 cancellation guard (NaN-proof)
    float d = fmaf(EPS_F, w * w, dcore);
    float r;
    asm("rsqrt.approx.f32 %0, %1;" : "=f"(r) : "f"(d));
    return num * r;
}

extern __shared__ float s_buf[];

__global__ void __launch_bounds__(TPB)
ema_norm_kernel(const float* __restrict__ x, float* __restrict__ y)
{
    __shared__ float tv1[NWARP], tv2[NWARP], tm[NWARP];

    const int tid  = threadIdx.x;
    const int lane = tid & 31;
    const int wid  = tid >> 5;
    const size_t base = (size_t)blockIdx.x * T_LEN;

    // ---- async vector load: 8 x cp.async.cg of 16B per thread ----
    #pragma unroll
    for (int k = 0; k < T_LEN / (TPB * 4); k++) {
        int i4 = 4 * tid + k * (TPB * 4);     // float index, 16B aligned
        cp_async16(s_buf + PAD(i4), x + base + i4);
    }
    asm volatile("cp.async.commit_group;");
    asm volatile("cp.async.wait_group 0;" ::: "memory");
    __syncthreads();

    // ---- pass 1: segment-local EMA sums from zero state (LDS.128) ----
    const int t0 = tid * KP;
    const float4* row = reinterpret_cast<const float4*>(s_buf + PAD(t0));
    float L1 = 0.f, L2 = 0.f;
    #pragma unroll
    for (int i = 0; i < KP / 4; i++) {
        float4 v = row[i];
        warm_step(v.x, L1, L2);
        warm_step(v.y, L1, L2);
        warm_step(v.z, L1, L2);
        warm_step(v.w, L1, L2);
    }

    // ---- affine inclusive scan within warp: (v, m) ; combine = vR + mR*vL ----
    float v1 = L1, v2 = L2, m = A32_F;
    #pragma unroll
    for (int d = 1; d < 32; d <<= 1) {
        float pv1 = __shfl_up_sync(0xffffffffu, v1, d);
        float pv2 = __shfl_up_sync(0xffffffffu, v2, d);
        float pm  = __shfl_up_sync(0xffffffffu, m,  d);
        if (lane >= d) {
            v1 = fmaf(m, pv1, v1);
            v2 = fmaf(m, pv2, v2);
            m *= pm;
        }
    }
    // within-warp exclusive
    float ev1 = __shfl_up_sync(0xffffffffu, v1, 1);
    float ev2 = __shfl_up_sync(0xffffffffu, v2, 1);
    float em  = __shfl_up_sync(0xffffffffu, m,  1);
    if (lane == 0) { ev1 = 0.f; ev2 = 0.f; em = 1.f; }

    // cross-warp: publish warp totals, combine serially (16 entries)
    if (lane == 31) { tv1[wid] = v1; tv2[wid] = v2; tm[wid] = m; }
    __syncthreads();
    float p1 = 0.f, p2 = 0.f, pm = 1.f;
    for (int j = 0; j < wid; j++) {           // oldest-first composition
        p1 = fmaf(tm[j], p1, tv1[j]);
        p2 = fmaf(tm[j], p2, tv2[j]);
        pm *= tm[j];
    }
    float s1 = fmaf(em, p1, ev1);
    float s2 = fmaf(em, p2, ev2);
    float w  = 1.0f - pm * em;                // 1 - alpha^{t0}

    // ---- pass 2: normalize 32 steps from exact state, in-place (128-bit) ----
    float4* rw = reinterpret_cast<float4*>(s_buf + PAD(t0));
    #pragma unroll
    for (int i = 0; i < KP / 4; i++) {
        float4 v = rw[i];
        float4 o;
        o.x = ema_step(v.x, s1, s2, w);
        o.y = ema_step(v.y, s1, s2, w);
        o.z = ema_step(v.z, s1, s2, w);
        o.w = ema_step(v.w, s1, s2, w);
        rw[i] = o;
    }
    __syncthreads();

    // ---- vector store: LDS.128 + STG.128, coalesced ----
    #pragma unroll
    for (int k = 0; k < T_LEN / (TPB * 4); k++) {
        int i4 = 4 * tid + k * (TPB * 4);
        float4 v = *reinterpret_cast<const float4*>(s_buf + PAD(i4));
        *reinterpret_cast<float4*>(y + base + i4) = v;
    }
}

extern "C" void kernel_launch(void* const* d_in, const int* in_sizes, int n_in,
                              void* d_out, int out_size) {
    const float* x = (const float*)d_in[0];
    float*       y = (float*)d_out;

    int total = in_sizes[0];            // B*C*T
    int lanes = total / T_LEN;          // 2048 blocks, one per lane

    cudaFuncSetAttribute(ema_norm_kernel,
                         cudaFuncAttributeMaxDynamicSharedMemorySize,
                         SMEM_F * sizeof(float));
    ema_norm_kernel<<<lanes, TPB, SMEM_F * sizeof(float)>>>(x, y);
}